// round 6
// baseline (speedup 1.0000x reference)
#include <cuda_runtime.h>
#include <cstdint>

#define B_ 2
#define H_ 8
#define S_ 1024
#define DK_ 64
#define DV_ 64
static constexpr float INV_T = 0.125f;                   // 1/temperature
static constexpr int OUT_ATTN_OFF = B_ * H_ * S_ * DV_;  // 1048576

// ---- packed fp32 helpers (sm_103a f32x2 pipe) -------------------------------
#define FMA2(acc, a, b) asm("fma.rn.f32x2 %0, %1, %2, %0;" : "+l"(acc) : "l"(a), "l"(b))

__device__ __forceinline__ unsigned long long dup2(float x) {
    unsigned long long r;
    asm("mov.b64 %0, {%1, %1};" : "=l"(r) : "f"(x));
    return r;
}
__device__ __forceinline__ float2 unpack2(unsigned long long v) {
    float2 r;
    asm("mov.b64 {%0, %1}, %2;" : "=f"(r.x), "=f"(r.y) : "l"(v));
    return r;
}

// ---- cp.async helpers -------------------------------------------------------
__device__ __forceinline__ uint32_t s2u(const void* p) {
    return (uint32_t)__cvta_generic_to_shared(p);
}
__device__ __forceinline__ void cp8(uint32_t dst, const void* src) {
    asm volatile("cp.async.ca.shared.global [%0], [%1], 8;" :: "r"(dst), "l"(src));
}
__device__ __forceinline__ void cp16(uint32_t dst, const void* src) {
    asm volatile("cp.async.cg.shared.global [%0], [%1], 16;" :: "r"(dst), "l"(src));
}
#define CP_COMMIT() asm volatile("cp.async.commit_group;")
#define CP_WAIT1()  asm volatile("cp.async.wait_group 1;")
#define CP_WAIT0()  asm volatile("cp.async.wait_group 0;")

// ---------------------------------------------------------------------------
// K1: attn1[b,h,i,j] = (q/T)[b,h,i,:] . k[b,h,j,:]
// 128x128 CTA tile, 512 threads (2 CTAs/SM forced), per-thread 4x8 micro-tile
// with SPLIT j-blocks (4tx..4tx+3 and 64+4tx..) so K LDS.128s are contiguous
// and bank-conflict-free. f32x2 accumulators over i-pairs.
// ---------------------------------------------------------------------------
static constexpr int K1_PITCH = 132;
static constexpr int K1_SMEM = 2 * 64 * K1_PITCH * 4;  // 67584 B

__global__ void __launch_bounds__(512, 2) k1_qk(const float* __restrict__ q,
                                                const float* __restrict__ k,
                                                float* __restrict__ attn)
{
    extern __shared__ float sm1[];
    float* Qt = sm1;                   // [64][132]  Qt[d][i], pre-scaled by 1/T
    float* Kt = sm1 + 64 * K1_PITCH;   // [64][132]  Kt[d][j]

    const int bh = blockIdx.z;
    const int i0 = blockIdx.y * 128;
    const int j0 = blockIdx.x * 128;
    const float* qb = q + ((size_t)bh * S_ + i0) * DK_;
    const float* kb = k + ((size_t)bh * S_ + j0) * DK_;
    const int t = threadIdx.x;

    #pragma unroll
    for (int idx = t; idx < 2048; idx += 512) {
        const int row = idx & 127;
        const int d4  = ((idx >> 7) & 15) << 2;
        float4 a = *(const float4*)(qb + (size_t)row * DK_ + d4);
        Qt[(d4 + 0) * K1_PITCH + row] = a.x * INV_T;
        Qt[(d4 + 1) * K1_PITCH + row] = a.y * INV_T;
        Qt[(d4 + 2) * K1_PITCH + row] = a.z * INV_T;
        Qt[(d4 + 3) * K1_PITCH + row] = a.w * INV_T;
        float4 b = *(const float4*)(kb + (size_t)row * DK_ + d4);
        Kt[(d4 + 0) * K1_PITCH + row] = b.x;
        Kt[(d4 + 1) * K1_PITCH + row] = b.y;
        Kt[(d4 + 2) * K1_PITCH + row] = b.z;
        Kt[(d4 + 3) * K1_PITCH + row] = b.w;
    }
    __syncthreads();

    const int tx = t & 15;   // j: cols 4tx..4tx+3 and 64+4tx..64+4tx+3
    const int ty = t >> 4;   // i: rows 4ty..4ty+3
    const float* qp = Qt + ty * 4;
    const float* kp = Kt + tx * 4;

    unsigned long long acc[2][8] = {};  // [i-pair p][v: 0-3 lo blk, 4-7 hi blk]

    #pragma unroll 4
    for (int d = 0; d < 64; d++) {
        const float* qd = qp + d * K1_PITCH;
        const float* kd = kp + d * K1_PITCH;
        ulonglong2 a = *(const ulonglong2*)qd;   // (i4ty,i4ty+1),(i4ty+2,i4ty+3)
        float4 b0 = *(const float4*)kd;          // contiguous, conflict-free
        float4 b1 = *(const float4*)(kd + 64);
        unsigned long long bb[8] = {dup2(b0.x), dup2(b0.y), dup2(b0.z), dup2(b0.w),
                                    dup2(b1.x), dup2(b1.y), dup2(b1.z), dup2(b1.w)};
        #pragma unroll
        for (int v = 0; v < 8; v++) FMA2(acc[0][v], a.x, bb[v]);
        #pragma unroll
        for (int v = 0; v < 8; v++) FMA2(acc[1][v], a.y, bb[v]);
    }

    float* ab = attn + (((size_t)bh * S_ + i0 + ty * 4) * S_) + j0;
    #pragma unroll
    for (int p = 0; p < 2; p++) {
        float r0[8], r1[8];
        #pragma unroll
        for (int v = 0; v < 8; v++) {
            float2 pv = unpack2(acc[p][v]);
            r0[v] = pv.x; r1[v] = pv.y;
        }
        float* row0 = ab + (size_t)(2 * p) * S_;
        float* row1 = ab + (size_t)(2 * p + 1) * S_;
        *(float4*)(row0 + 4 * tx)      = make_float4(r0[0], r0[1], r0[2], r0[3]);
        *(float4*)(row0 + 64 + 4 * tx) = make_float4(r0[4], r0[5], r0[6], r0[7]);
        *(float4*)(row1 + 4 * tx)      = make_float4(r1[0], r1[1], r1[2], r1[3]);
        *(float4*)(row1 + 64 + 4 * tx) = make_float4(r1[4], r1[5], r1[6], r1[7]);
    }
}

// ---------------------------------------------------------------------------
// K2: per (b,i): logits[h][j] = attn1[h][j] + qs[h,:] . rpr[b,i,j,:]
//     mask, softmax over j, write final probs. rpr streamed exactly once.
// qs packed [d][h] -> one uniform LDS.128 feeds 2 head-pair FMA2s.
// Single rs buffer (102 KB total smem) -> 2 CTAs/SM for stage/compute overlap
// across CTAs; staging via coalesced cp.async.
// ---------------------------------------------------------------------------
static constexpr int K2_CHUNK = 256;
static constexpr int K2_PITCH = 66;
static constexpr int K2_RS_FLOATS = K2_CHUNK * K2_PITCH;          // 16896
static constexpr int K2_SMEM_TOTAL = (512 + 8192 + K2_RS_FLOATS) * 4;  // 102400 B

__global__ void __launch_bounds__(256, 2) k2_rpr_softmax(
    const float* __restrict__ q,
    const float* __restrict__ rpr,
    const int* __restrict__ mask,
    float* __restrict__ attn)
{
    extern __shared__ float sm2[];
    float* qs2   = sm2;                       // [64][8]: qs2[d*8+h]
    float* logit = sm2 + 512;                 // [8][1024]
    float* rs    = sm2 + 512 + 8192;          // [256][66]

    const int b = blockIdx.y;
    const int i = blockIdx.x;
    const int t = threadIdx.x;

    // qs2[d][h] = q[b,h,i,d] / T  (h fastest => one 16B row-slice = 4 heads)
    #pragma unroll
    for (int idx = t; idx < 512; idx += 256) {
        const int h = idx & 7, d = idx >> 3;
        qs2[d * 8 + h] = q[(((size_t)b * H_ + h) * S_ + i) * DK_ + d] * INV_T;
    }

    const float* rbase = rpr + ((size_t)b * S_ + i) * S_ * DK_;
    const int* mrow = mask + ((size_t)b * S_ + i) * S_;
    const uint32_t rs_u = s2u(rs);

    #pragma unroll
    for (int c = 0; c < 4; c++) {
        const int jc = c * K2_CHUNK;
        const int j = jc + t;
        __syncthreads();   // previous chunk fully consumed (and qs2 ready)

        // stage rpr chunk (coalesced 8B cp.async into pitch-66 layout)
        const float* src = rbase + (size_t)jc * DK_;
        #pragma unroll
        for (int m = 0; m < 32; m++) {
            const int idx = m * 256 + t;
            const int jj  = idx >> 5;
            const int d2  = (idx & 31) << 1;
            cp8(rs_u + (uint32_t)(jj * K2_PITCH + d2) * 4u, src + idx * 2);
        }
        CP_COMMIT();

        // prefetch mask + attn1 while cp.async is in flight
        const int mk = mrow[j];
        float a1v[8];
        #pragma unroll
        for (int h = 0; h < 8; h++)
            a1v[h] = attn[(((size_t)b * H_ + h) * S_ + i) * S_ + j];

        CP_WAIT0();
        __syncthreads();

        unsigned long long acc[4] = {};  // head pairs packed
        const float* rr = rs + t * K2_PITCH;
        #pragma unroll
        for (int d4 = 0; d4 < 16; d4++) {
            float2 ra = *(const float2*)(rr + d4 * 4);
            float2 rb = *(const float2*)(rr + d4 * 4 + 2);
            const float rv[4] = {ra.x, ra.y, rb.x, rb.y};
            #pragma unroll
            for (int dd = 0; dd < 4; dd++) {
                const int d = d4 * 4 + dd;
                ulonglong2 qA = *(const ulonglong2*)(qs2 + d * 8);      // h0..3
                ulonglong2 qB = *(const ulonglong2*)(qs2 + d * 8 + 4);  // h4..7
                unsigned long long rd = dup2(rv[dd]);
                FMA2(acc[0], qA.x, rd);
                FMA2(acc[1], qA.y, rd);
                FMA2(acc[2], qB.x, rd);
                FMA2(acc[3], qB.y, rd);
            }
        }

        #pragma unroll
        for (int hp = 0; hp < 4; hp++) {
            float2 av = unpack2(acc[hp]);
            logit[(2 * hp)     * 1024 + j] = mk ? (av.x + a1v[2 * hp])     : -1e9f;
            logit[(2 * hp + 1) * 1024 + j] = mk ? (av.y + a1v[2 * hp + 1]) : -1e9f;
        }
    }
    __syncthreads();

    // softmax: warp w handles head w
    const int w = t >> 5, lane = t & 31;
    const float* lrow = logit + w * 1024;
    float vals[32];
    float mx = -3.4e38f;
    #pragma unroll
    for (int m = 0; m < 32; m++) {
        vals[m] = lrow[lane + 32 * m];
        mx = fmaxf(mx, vals[m]);
    }
    #pragma unroll
    for (int o = 16; o > 0; o >>= 1) mx = fmaxf(mx, __shfl_xor_sync(0xffffffffu, mx, o));
    float sum = 0.f;
    #pragma unroll
    for (int m = 0; m < 32; m++) { vals[m] = __expf(vals[m] - mx); sum += vals[m]; }
    #pragma unroll
    for (int o = 16; o > 0; o >>= 1) sum += __shfl_xor_sync(0xffffffffu, sum, o);
    const float rinv = 1.0f / sum;

    float* arow = attn + (((size_t)b * H_ + w) * S_ + i) * S_;
    #pragma unroll
    for (int m = 0; m < 32; m++) arow[lane + 32 * m] = vals[m] * rinv;
}

// ---------------------------------------------------------------------------
// K3: output[b,h,i,:] = sum_j attn[b,h,i,j] * v[b,h,j,:]
// Broadcast-A, f32x2 accumulators, double-buffered cp.async (unchanged).
// ---------------------------------------------------------------------------
static constexpr int K3_TILE_FLOATS = 64 * 64;                     // 4096
static constexpr int K3_SMEM = 4 * K3_TILE_FLOATS * 4;             // 65536 B

__device__ __forceinline__ void k3_stage(uint32_t as_u, uint32_t vs_u,
                                         const float* __restrict__ ab,
                                         const float* __restrict__ vb,
                                         int jc, int t)
{
    #pragma unroll
    for (int m = 0; m < 4; m++) {
        const int idx = m * 256 + t;
        const int row = idx >> 4;
        const int d4  = (idx & 15) << 2;
        cp16(as_u + (uint32_t)(row * 64 + d4) * 4u, ab + (size_t)row * S_ + jc + d4);
        cp16(vs_u + (uint32_t)(row * 64 + d4) * 4u, vb + (size_t)(jc + row) * DV_ + d4);
    }
    CP_COMMIT();
}

__global__ void __launch_bounds__(256) k3_av(const float* __restrict__ attn,
                                             const float* __restrict__ v,
                                             float* __restrict__ out)
{
    extern __shared__ float sm3[];
    float* Asb[2] = { sm3,                      sm3 + 2 * K3_TILE_FLOATS };
    float* Vsb[2] = { sm3 + K3_TILE_FLOATS,     sm3 + 3 * K3_TILE_FLOATS };

    const int bh = blockIdx.y;
    const int i0 = blockIdx.x * 64;
    const int t = threadIdx.x;
    const int w = t >> 5, l = t & 31;
    const float* ab = attn + ((size_t)bh * S_ + i0) * S_;
    const float* vb = v + (size_t)bh * S_ * DV_;
    const uint32_t as_u[2] = { s2u(Asb[0]), s2u(Asb[1]) };
    const uint32_t vs_u[2] = { s2u(Vsb[0]), s2u(Vsb[1]) };

    unsigned long long acc[8] = {};

    k3_stage(as_u[0], vs_u[0], ab, vb, 0, t);

    for (int c = 0; c < 16; c++) {
        if (c < 15) {
            k3_stage(as_u[(c + 1) & 1], vs_u[(c + 1) & 1], ab, vb, (c + 1) * 64, t);
            CP_WAIT1();
        } else {
            CP_WAIT0();
        }
        __syncthreads();

        const float* As = Asb[c & 1];
        const float* Vs = Vsb[c & 1];
        #pragma unroll 4
        for (int j4 = 0; j4 < 64; j4 += 4) {
            unsigned long long vv[4];
            #pragma unroll
            for (int kk = 0; kk < 4; kk++)
                vv[kk] = *(const unsigned long long*)&Vs[(j4 + kk) * 64 + l * 2];
            #pragma unroll
            for (int r = 0; r < 8; r++) {
                float4 a4 = *(const float4*)&As[(w * 8 + r) * 64 + j4];  // broadcast
                FMA2(acc[r], dup2(a4.x), vv[0]);
                FMA2(acc[r], dup2(a4.y), vv[1]);
                FMA2(acc[r], dup2(a4.z), vv[2]);
                FMA2(acc[r], dup2(a4.w), vv[3]);
            }
        }
        __syncthreads();   // tile consumed before it is restaged
    }

    float* ob = out + ((size_t)bh * S_ + i0 + w * 8) * DV_ + l * 2;
    #pragma unroll
    for (int r = 0; r < 8; r++) {
        float2 o = unpack2(acc[r]);
        *(float2*)(ob + (size_t)r * DV_) = o;
    }
}

// ---------------------------------------------------------------------------
extern "C" void kernel_launch(void* const* d_in, const int* in_sizes, int n_in,
                              void* d_out, int out_size)
{
    const float* q    = (const float*)d_in[0];
    const float* k    = (const float*)d_in[1];
    const float* v    = (const float*)d_in[2];
    const int*   mask = (const int*)d_in[3];
    const float* rpr  = (const float*)d_in[4];
    float* out  = (float*)d_out;
    float* attn = out + OUT_ATTN_OFF;

    cudaFuncSetAttribute(k1_qk, cudaFuncAttributeMaxDynamicSharedMemorySize, K1_SMEM);
    cudaFuncSetAttribute(k2_rpr_softmax, cudaFuncAttributeMaxDynamicSharedMemorySize,
                         K2_SMEM_TOTAL);
    cudaFuncSetAttribute(k3_av, cudaFuncAttributeMaxDynamicSharedMemorySize, K3_SMEM);

    {   // K1: attn1 logits into attn region (scratch, rewritten by K2)
        dim3 grid(S_ / 128, S_ / 128, B_ * H_);
        k1_qk<<<grid, 512, K1_SMEM>>>(q, k, attn);
    }
    {   // K2: + positional term, mask, softmax (in place)
        dim3 grid(S_, B_);
        k2_rpr_softmax<<<grid, 256, K2_SMEM_TOTAL>>>(q, rpr, mask, attn);
    }
    {   // K3: output = attn @ v
        dim3 grid(S_ / 64, B_ * H_);
        k3_av<<<grid, 256, K3_SMEM>>>(attn, v, out);
    }
}

// round 7
// speedup vs baseline: 1.0463x; 1.0463x over previous
#include <cuda_runtime.h>
#include <cstdint>

#define B_ 2
#define H_ 8
#define S_ 1024
#define DK_ 64
#define DV_ 64
static constexpr float INV_T = 0.125f;                   // 1/temperature
static constexpr int OUT_ATTN_OFF = B_ * H_ * S_ * DV_;  // 1048576

// ---- packed fp32 helpers (sm_103a f32x2 pipe) -------------------------------
#define FMA2(acc, a, b) asm("fma.rn.f32x2 %0, %1, %2, %0;" : "+l"(acc) : "l"(a), "l"(b))

__device__ __forceinline__ unsigned long long dup2(float x) {
    unsigned long long r;
    asm("mov.b64 %0, {%1, %1};" : "=l"(r) : "f"(x));
    return r;
}
__device__ __forceinline__ float2 unpack2(unsigned long long v) {
    float2 r;
    asm("mov.b64 {%0, %1}, %2;" : "=f"(r.x), "=f"(r.y) : "l"(v));
    return r;
}

// ---- cp.async helpers -------------------------------------------------------
__device__ __forceinline__ uint32_t s2u(const void* p) {
    return (uint32_t)__cvta_generic_to_shared(p);
}
__device__ __forceinline__ void cp16(uint32_t dst, const void* src) {
    asm volatile("cp.async.cg.shared.global [%0], [%1], 16;" :: "r"(dst), "l"(src));
}
#define CP_COMMIT() asm volatile("cp.async.commit_group;")
#define CP_WAIT1()  asm volatile("cp.async.wait_group 1;")
#define CP_WAIT0()  asm volatile("cp.async.wait_group 0;")

// ---------------------------------------------------------------------------
// K1: attn1[b,h,i,j] = (q/T)[b,h,i,:] . k[b,h,j,:]   (unchanged from R5)
// 128x128 CTA tile, 512 threads, 4x8 split micro-tile, f32x2 accumulators.
// ---------------------------------------------------------------------------
static constexpr int K1_PITCH = 132;
static constexpr int K1_SMEM = 2 * 64 * K1_PITCH * 4;  // 67584 B

__global__ void __launch_bounds__(512, 2) k1_qk(const float* __restrict__ q,
                                                const float* __restrict__ k,
                                                float* __restrict__ attn)
{
    extern __shared__ float sm1[];
    float* Qt = sm1;                   // [64][132]  Qt[d][i], pre-scaled by 1/T
    float* Kt = sm1 + 64 * K1_PITCH;   // [64][132]  Kt[d][j]

    const int bh = blockIdx.z;
    const int i0 = blockIdx.y * 128;
    const int j0 = blockIdx.x * 128;
    const float* qb = q + ((size_t)bh * S_ + i0) * DK_;
    const float* kb = k + ((size_t)bh * S_ + j0) * DK_;
    const int t = threadIdx.x;

    #pragma unroll
    for (int idx = t; idx < 2048; idx += 512) {
        const int row = idx & 127;
        const int d4  = ((idx >> 7) & 15) << 2;
        float4 a = *(const float4*)(qb + (size_t)row * DK_ + d4);
        Qt[(d4 + 0) * K1_PITCH + row] = a.x * INV_T;
        Qt[(d4 + 1) * K1_PITCH + row] = a.y * INV_T;
        Qt[(d4 + 2) * K1_PITCH + row] = a.z * INV_T;
        Qt[(d4 + 3) * K1_PITCH + row] = a.w * INV_T;
        float4 b = *(const float4*)(kb + (size_t)row * DK_ + d4);
        Kt[(d4 + 0) * K1_PITCH + row] = b.x;
        Kt[(d4 + 1) * K1_PITCH + row] = b.y;
        Kt[(d4 + 2) * K1_PITCH + row] = b.z;
        Kt[(d4 + 3) * K1_PITCH + row] = b.w;
    }
    __syncthreads();

    const int tx = t & 15;
    const int ty = t >> 4;
    const float* qp = Qt + ty * 4;
    const float* kp = Kt + tx * 4;

    unsigned long long acc[2][8] = {};

    #pragma unroll 4
    for (int d = 0; d < 64; d++) {
        const float* qd = qp + d * K1_PITCH;
        const float* kd = kp + d * K1_PITCH;
        ulonglong2 a = *(const ulonglong2*)qd;
        float4 b0 = *(const float4*)kd;
        float4 b1 = *(const float4*)(kd + 64);
        unsigned long long bb[8] = {dup2(b0.x), dup2(b0.y), dup2(b0.z), dup2(b0.w),
                                    dup2(b1.x), dup2(b1.y), dup2(b1.z), dup2(b1.w)};
        #pragma unroll
        for (int v = 0; v < 8; v++) FMA2(acc[0][v], a.x, bb[v]);
        #pragma unroll
        for (int v = 0; v < 8; v++) FMA2(acc[1][v], a.y, bb[v]);
    }

    float* ab = attn + (((size_t)bh * S_ + i0 + ty * 4) * S_) + j0;
    #pragma unroll
    for (int p = 0; p < 2; p++) {
        float r0[8], r1[8];
        #pragma unroll
        for (int v = 0; v < 8; v++) {
            float2 pv = unpack2(acc[p][v]);
            r0[v] = pv.x; r1[v] = pv.y;
        }
        float* row0 = ab + (size_t)(2 * p) * S_;
        float* row1 = ab + (size_t)(2 * p + 1) * S_;
        *(float4*)(row0 + 4 * tx)      = make_float4(r0[0], r0[1], r0[2], r0[3]);
        *(float4*)(row0 + 64 + 4 * tx) = make_float4(r0[4], r0[5], r0[6], r0[7]);
        *(float4*)(row1 + 4 * tx)      = make_float4(r1[0], r1[1], r1[2], r1[3]);
        *(float4*)(row1 + 64 + 4 * tx) = make_float4(r1[4], r1[5], r1[6], r1[7]);
    }
}

// ---------------------------------------------------------------------------
// K2 (REBUILT): per (b,i): logits[h][j] = attn1[h][j] + qs[h,:].rpr[b,i,j,:]
//   mask, softmax over j, write probs. rpr streamed once via a TRUE in-CTA
//   double-buffered cp16 pipeline (next chunk always in flight), pitch-68
//   conflict-free layout, logits held in registers (thread t owns
//   j = c*256+t for all 8 heads), block softmax via shuffles + tiny smem.
// ---------------------------------------------------------------------------
static constexpr int K2_CHUNK = 256;
static constexpr int K2_PITCH = 68;                        // 16B rows, xbar-clean
static constexpr int K2_BUF = K2_CHUNK * K2_PITCH;         // 17408 floats
static constexpr int K2_SMEM_TOTAL = (512 + 128 + 2 * K2_BUF) * 4;  // 141824 B

__device__ __forceinline__ void k2_stage(uint32_t rs_u, const float* __restrict__ src,
                                         int t)
{
    // 256 rows x 16 float4 groups; idx->(j=idx>>4, g=idx&15): coalesced 16B
    #pragma unroll
    for (int m = 0; m < 16; m++) {
        const int idx = m * 256 + t;
        const int j = idx >> 4;
        const int g = idx & 15;
        cp16(rs_u + (uint32_t)(j * K2_PITCH + g * 4) * 4u, src + (size_t)idx * 4);
    }
    CP_COMMIT();
}

__global__ void __launch_bounds__(256, 1) k2_rpr_softmax(
    const float* __restrict__ q,
    const float* __restrict__ rpr,
    const int* __restrict__ mask,
    float* __restrict__ attn)
{
    extern __shared__ float sm2[];
    float* qs2  = sm2;            // [64][8]: qs2[d*8+h] = q[h][d]/T
    float* redm = sm2 + 512;      // [8][8] partial reductions
    float* fval = sm2 + 576;      // [8] per-head max / inv-sum
    float* rs0  = sm2 + 640;      // [256][68]
    float* rs1  = rs0 + K2_BUF;   // [256][68]

    const int b = blockIdx.y;
    const int i = blockIdx.x;
    const int t = threadIdx.x;
    const int w = t >> 5, lane = t & 31;

    // qs2[d][h] = q[b,h,i,d] / T
    #pragma unroll
    for (int idx = t; idx < 512; idx += 256) {
        const int h = idx & 7, d = idx >> 3;
        qs2[d * 8 + h] = q[(((size_t)b * H_ + h) * S_ + i) * DK_ + d] * INV_T;
    }

    const float* rbase = rpr + ((size_t)b * S_ + i) * S_ * DK_;
    const int* mrow = mask + ((size_t)b * S_ + i) * S_;
    const uint32_t ru[2] = { s2u(rs0), s2u(rs1) };
    const float* rp[2] = { rs0, rs1 };

    float l[8][4];                      // logits: [head][chunk], j = c*256+t

    k2_stage(ru[0], rbase, t);          // prologue: chunk 0 in flight

    #pragma unroll
    for (int c = 0; c < 4; c++) {
        if (c) __syncthreads();         // readers of buf[(c+1)&1] (iter c-1) done

        const int j = c * K2_CHUNK + t;
        const int mk = mrow[j];
        float a1v[8];                   // attn1 prefetch (coalesced, overlaps cp)
        #pragma unroll
        for (int h = 0; h < 8; h++)
            a1v[h] = attn[(((size_t)b * H_ + h) * S_ + i) * S_ + j];

        if (c < 3) {                    // keep next chunk in flight during compute
            k2_stage(ru[(c + 1) & 1], rbase + (size_t)(c + 1) * K2_CHUNK * DK_, t);
            CP_WAIT1();
        } else {
            CP_WAIT0();
        }
        __syncthreads();                // all threads' copies of buf[c&1] visible

        unsigned long long acc[4] = {};
        const float* rr = rp[c & 1] + t * K2_PITCH;   // own row, conflict-free
        #pragma unroll
        for (int g = 0; g < 16; g++) {
            float4 r4 = *(const float4*)(rr + g * 4);
            const float rv[4] = {r4.x, r4.y, r4.z, r4.w};
            #pragma unroll
            for (int e = 0; e < 4; e++) {
                const int d = g * 4 + e;
                ulonglong2 qA = *(const ulonglong2*)(qs2 + d * 8);      // h0..3
                ulonglong2 qB = *(const ulonglong2*)(qs2 + d * 8 + 4);  // h4..7
                unsigned long long rd = dup2(rv[e]);
                FMA2(acc[0], qA.x, rd);
                FMA2(acc[1], qA.y, rd);
                FMA2(acc[2], qB.x, rd);
                FMA2(acc[3], qB.y, rd);
            }
        }

        #pragma unroll
        for (int hp = 0; hp < 4; hp++) {
            float2 av = unpack2(acc[hp]);
            l[2 * hp][c]     = mk ? (av.x + a1v[2 * hp])     : -1e9f;
            l[2 * hp + 1][c] = mk ? (av.y + a1v[2 * hp + 1]) : -1e9f;
        }
    }

    // ---- block softmax over j (1024 values spread across 256 threads x 4) ----
    // per-head max
    #pragma unroll
    for (int h = 0; h < 8; h++) {
        float m = fmaxf(fmaxf(l[h][0], l[h][1]), fmaxf(l[h][2], l[h][3]));
        #pragma unroll
        for (int o = 16; o > 0; o >>= 1)
            m = fmaxf(m, __shfl_xor_sync(0xffffffffu, m, o));
        if (lane == 0) redm[h * 8 + w] = m;
    }
    __syncthreads();
    {   // warp w finalizes head w (width-8 reduce over 8 warp partials)
        float m2 = redm[w * 8 + (lane & 7)];
        #pragma unroll
        for (int o = 4; o > 0; o >>= 1)
            m2 = fmaxf(m2, __shfl_xor_sync(0xffffffffu, m2, o, 8));
        if (lane == 0) fval[w] = m2;
    }
    __syncthreads();
    float mxs[8];
    #pragma unroll
    for (int h = 0; h < 8; h++) mxs[h] = fval[h];
    __syncthreads();            // redm safe to reuse

    // exp + per-head sum
    #pragma unroll
    for (int h = 0; h < 8; h++) {
        float s = 0.f;
        #pragma unroll
        for (int c = 0; c < 4; c++) {
            l[h][c] = __expf(l[h][c] - mxs[h]);
            s += l[h][c];
        }
        #pragma unroll
        for (int o = 16; o > 0; o >>= 1)
            s += __shfl_xor_sync(0xffffffffu, s, o);
        if (lane == 0) redm[h * 8 + w] = s;
    }
    __syncthreads();
    {
        float s2 = redm[w * 8 + (lane & 7)];
        #pragma unroll
        for (int o = 4; o > 0; o >>= 1)
            s2 += __shfl_xor_sync(0xffffffffu, s2, o, 8);
        if (lane == 0) fval[w] = 1.0f / s2;
    }
    __syncthreads();

    // write probabilities (coalesced per (h,c))
    #pragma unroll
    for (int h = 0; h < 8; h++) {
        const float rinv = fval[h];
        float* arow = attn + (((size_t)b * H_ + h) * S_ + i) * S_;
        #pragma unroll
        for (int c = 0; c < 4; c++)
            arow[c * K2_CHUNK + t] = l[h][c] * rinv;
    }
}

// ---------------------------------------------------------------------------
// K3: output[b,h,i,:] = sum_j attn[b,h,i,j] * v[b,h,j,:]   (unchanged from R5)
// ---------------------------------------------------------------------------
static constexpr int K3_TILE_FLOATS = 64 * 64;                     // 4096
static constexpr int K3_SMEM = 4 * K3_TILE_FLOATS * 4;             // 65536 B

__device__ __forceinline__ void k3_stage(uint32_t as_u, uint32_t vs_u,
                                         const float* __restrict__ ab,
                                         const float* __restrict__ vb,
                                         int jc, int t)
{
    #pragma unroll
    for (int m = 0; m < 4; m++) {
        const int idx = m * 256 + t;
        const int row = idx >> 4;
        const int d4  = (idx & 15) << 2;
        cp16(as_u + (uint32_t)(row * 64 + d4) * 4u, ab + (size_t)row * S_ + jc + d4);
        cp16(vs_u + (uint32_t)(row * 64 + d4) * 4u, vb + (size_t)(jc + row) * DV_ + d4);
    }
    CP_COMMIT();
}

__global__ void __launch_bounds__(256) k3_av(const float* __restrict__ attn,
                                             const float* __restrict__ v,
                                             float* __restrict__ out)
{
    extern __shared__ float sm3[];
    float* Asb[2] = { sm3,                      sm3 + 2 * K3_TILE_FLOATS };
    float* Vsb[2] = { sm3 + K3_TILE_FLOATS,     sm3 + 3 * K3_TILE_FLOATS };

    const int bh = blockIdx.y;
    const int i0 = blockIdx.x * 64;
    const int t = threadIdx.x;
    const int w = t >> 5, l = t & 31;
    const float* ab = attn + ((size_t)bh * S_ + i0) * S_;
    const float* vb = v + (size_t)bh * S_ * DV_;
    const uint32_t as_u[2] = { s2u(Asb[0]), s2u(Asb[1]) };
    const uint32_t vs_u[2] = { s2u(Vsb[0]), s2u(Vsb[1]) };

    unsigned long long acc[8] = {};

    k3_stage(as_u[0], vs_u[0], ab, vb, 0, t);

    for (int c = 0; c < 16; c++) {
        if (c < 15) {
            k3_stage(as_u[(c + 1) & 1], vs_u[(c + 1) & 1], ab, vb, (c + 1) * 64, t);
            CP_WAIT1();
        } else {
            CP_WAIT0();
        }
        __syncthreads();

        const float* As = Asb[c & 1];
        const float* Vs = Vsb[c & 1];
        #pragma unroll 4
        for (int j4 = 0; j4 < 64; j4 += 4) {
            unsigned long long vv[4];
            #pragma unroll
            for (int kk = 0; kk < 4; kk++)
                vv[kk] = *(const unsigned long long*)&Vs[(j4 + kk) * 64 + l * 2];
            #pragma unroll
            for (int r = 0; r < 8; r++) {
                float4 a4 = *(const float4*)&As[(w * 8 + r) * 64 + j4];
                FMA2(acc[r], dup2(a4.x), vv[0]);
                FMA2(acc[r], dup2(a4.y), vv[1]);
                FMA2(acc[r], dup2(a4.z), vv[2]);
                FMA2(acc[r], dup2(a4.w), vv[3]);
            }
        }
        __syncthreads();
    }

    float* ob = out + ((size_t)bh * S_ + i0 + w * 8) * DV_ + l * 2;
    #pragma unroll
    for (int r = 0; r < 8; r++) {
        float2 o = unpack2(acc[r]);
        *(float2*)(ob + (size_t)r * DV_) = o;
    }
}

// ---------------------------------------------------------------------------
extern "C" void kernel_launch(void* const* d_in, const int* in_sizes, int n_in,
                              void* d_out, int out_size)
{
    const float* q    = (const float*)d_in[0];
    const float* k    = (const float*)d_in[1];
    const float* v    = (const float*)d_in[2];
    const int*   mask = (const int*)d_in[3];
    const float* rpr  = (const float*)d_in[4];
    float* out  = (float*)d_out;
    float* attn = out + OUT_ATTN_OFF;

    cudaFuncSetAttribute(k1_qk, cudaFuncAttributeMaxDynamicSharedMemorySize, K1_SMEM);
    cudaFuncSetAttribute(k2_rpr_softmax, cudaFuncAttributeMaxDynamicSharedMemorySize,
                         K2_SMEM_TOTAL);
    cudaFuncSetAttribute(k3_av, cudaFuncAttributeMaxDynamicSharedMemorySize, K3_SMEM);

    {   // K1: attn1 logits into attn region (scratch, rewritten by K2)
        dim3 grid(S_ / 128, S_ / 128, B_ * H_);
        k1_qk<<<grid, 512, K1_SMEM>>>(q, k, attn);
    }
    {   // K2: + positional term, mask, softmax
        dim3 grid(S_, B_);
        k2_rpr_softmax<<<grid, 256, K2_SMEM_TOTAL>>>(q, rpr, mask, attn);
    }
    {   // K3: output = attn @ v
        dim3 grid(S_ / 64, B_ * H_);
        k3_av<<<grid, 256, K3_SMEM>>>(attn, v, out);
    }
}